// round 9
// baseline (speedup 1.0000x reference)
#include <cuda_runtime.h>

// CBFHalfspace collapses analytically:
//   h(x) = [1+x0, 1-x0, 1+x1, 1-x1];  Lfh = Lf2h = 0, LgLfh = (0,0)  (affine h, A col-sums 0)
// Output row: [1+x0, 1-x0, 1+x1, 1-x1, 0,0,0,0]. f, g are dead inputs.
//
// R9: persistent R5. Same minimal-footprint body as R5 (regs ~30, 14 KB smem,
// warp-autonomous 64-row tiles, coalesced float4 loads -> smem -> contiguous
// float4 store sweep, .cs hints), but launched as a persistent grid of
// 8 blocks/SM x 152 SMs grid-striding over tiles: all 64 warps/SM stay
// resident for the whole kernel, removing block launch/drain churn.

#define THREADS 256
#define WARPS 8
#define ROWS_PER_TILE 64
#define F4_PER_TILE 112        // 64*7/4
#define OUT4_PER_TILE 128      // 64*2

__global__ void __launch_bounds__(THREADS)
cbf_kernel(const float4* __restrict__ x4, float4* __restrict__ out4,
           int n, int numTiles)
{
    __shared__ float buf[WARPS][ROWS_PER_TILE * 7];   // 14 KB

    const int lane = threadIdx.x & 31;
    const int wid  = threadIdx.x >> 5;

    float*  wbuf  = buf[wid];
    float4* wbufv = (float4*)wbuf;

    const int wstride = gridDim.x * WARPS;

    for (int t = blockIdx.x * WARPS + wid; t < numTiles; t += wstride) {
        const long long f4Base  = (long long)t * F4_PER_TILE;
        const long long outBase = (long long)t * OUT4_PER_TILE;
        const int rowsHere = n - t * ROWS_PER_TILE;

        if (rowsHere >= ROWS_PER_TILE) {
            // ---- fast path: full 64-row tile ----
            float4 r0 = __ldcs(&x4[f4Base +  0 + lane]);
            float4 r1 = __ldcs(&x4[f4Base + 32 + lane]);
            float4 r2 = __ldcs(&x4[f4Base + 64 + lane]);
            float4 r3;
            if (lane < 16) r3 = __ldcs(&x4[f4Base + 96 + lane]);
            wbufv[ 0 + lane] = r0;
            wbufv[32 + lane] = r1;
            wbufv[64 + lane] = r2;
            if (lane < 16) wbufv[96 + lane] = r3;
            __syncwarp();

            #pragma unroll
            for (int k = 0; k < 4; k++) {
                int idx = k * 32 + lane;            // 0..127, contiguous output sweep
                int row = idx >> 1;
                float4 v;
                if (idx & 1) {
                    v = make_float4(0.0f, 0.0f, 0.0f, 0.0f);
                } else {
                    float x0 = wbuf[row * 7 + 0];
                    float x1 = wbuf[row * 7 + 1];
                    v = make_float4(1.0f + x0, 1.0f - x0, 1.0f + x1, 1.0f - x1);
                }
                __stcs(&out4[outBase + idx], v);
            }
        } else {
            // ---- tail tile (generic, predicated) ----
            const int f4Here = (rowsHere * 7 + 3) >> 2;
            #pragma unroll
            for (int k = 0; k < 4; k++) {
                int idx = k * 32 + lane;
                if (idx < f4Here) wbufv[idx] = __ldcs(&x4[f4Base + idx]);
            }
            __syncwarp();
            #pragma unroll
            for (int k = 0; k < 4; k++) {
                int idx = k * 32 + lane;
                int row = idx >> 1;
                if (row < rowsHere) {
                    float4 v;
                    if (idx & 1) {
                        v = make_float4(0.0f, 0.0f, 0.0f, 0.0f);
                    } else {
                        float x0 = wbuf[row * 7 + 0];
                        float x1 = wbuf[row * 7 + 1];
                        v = make_float4(1.0f + x0, 1.0f - x0, 1.0f + x1, 1.0f - x1);
                    }
                    __stcs(&out4[outBase + idx], v);
                }
            }
        }
        __syncwarp();   // smem slice reuse fence before next iteration's refill
    }
}

extern "C" void kernel_launch(void* const* d_in, const int* in_sizes, int n_in,
                              void* d_out, int out_size)
{
    const float4* x4 = (const float4*)d_in[0];   // (B,7) fp32; B*7 divisible by 4
    float4* out4 = (float4*)d_out;               // (B,8) fp32 = 2 float4 per row

    const int n = in_sizes[0] / 7;               // B rows
    const int numTiles = (n + ROWS_PER_TILE - 1) / ROWS_PER_TILE;

    int blocksNeeded = (numTiles + WARPS - 1) / WARPS;
    int blocks = 152 * 8;                        // persistent: 8 blocks/SM on 152 SMs
    if (blocks > blocksNeeded) blocks = blocksNeeded;

    cbf_kernel<<<blocks, THREADS>>>(x4, out4, n, numTiles);
}

// round 10
// speedup vs baseline: 1.0530x; 1.0530x over previous
#include <cuda_runtime.h>

// CBFHalfspace collapses analytically:
//   h(x) = [1+x0, 1-x0, 1+x1, 1-x1];  Lfh = Lf2h = 0, LgLfh = (0,0)  (affine h, A col-sums 0)
// Output row: [1+x0, 1-x0, 1+x1, 1-x1, 0,0,0,0]. f, g are dead inputs.
//
// R10 = R5 (best measured config). Evidence from R8 (cp.async pipeline, -occ)
// and R9 (persistent grid, +occ but -DRAM) shows the kernel is at the sustained
// mixed read/write HBM ceiling (~6.1 TB/s for 251.7 MB minimal traffic); the
// minimal-footprint, warp-autonomous form is the fastest structure found.
//   - 64 rows/warp, 14 KB smem/block, ~30 regs -> 64 warps/SM resident.
//   - Loads: 3.5 coalesced LDG.128/lane (7 L1 lines per 32 rows = minimum).
//   - Stores: contiguous float4 sweep of the output (4 lines/wavefront = minimum).
//   - Warp-autonomous (__syncwarp only), .cs streaming hints both directions.

#define THREADS 256
#define WARPS (THREADS / 32)
#define ROWS_PER_WARP 64
#define ROWS_PER_BLOCK (WARPS * ROWS_PER_WARP)      // 512
#define F4_PER_WARP (ROWS_PER_WARP * 7 / 4)         // 112
#define OUT4_PER_WARP (ROWS_PER_WARP * 2)           // 128

__global__ void __launch_bounds__(THREADS)
cbf_kernel(const float4* __restrict__ x4, float4* __restrict__ out4, int n)
{
    __shared__ float buf[ROWS_PER_BLOCK * 7];       // 14 KB

    const int lane = threadIdx.x & 31;
    const int wid  = threadIdx.x >> 5;

    const int warpRow0 = blockIdx.x * ROWS_PER_BLOCK + wid * ROWS_PER_WARP;
    int rowsHere = n - warpRow0;
    if (rowsHere <= 0) return;

    float*  wbuf  = buf + wid * (ROWS_PER_WARP * 7);
    float4* wbufv = (float4*)wbuf;

    const long long f4Base  = (long long)warpRow0 * 7 / 4;   // warpRow0 % 4 == 0
    const long long outBase = (long long)warpRow0 * 2;

    if (rowsHere >= ROWS_PER_WARP) {
        // ---- fast path: full 64-row tile ----
        float4 r0 = __ldcs(&x4[f4Base +  0 + lane]);
        float4 r1 = __ldcs(&x4[f4Base + 32 + lane]);
        float4 r2 = __ldcs(&x4[f4Base + 64 + lane]);
        float4 r3;
        if (lane < 16) r3 = __ldcs(&x4[f4Base + 96 + lane]);
        wbufv[ 0 + lane] = r0;
        wbufv[32 + lane] = r1;
        wbufv[64 + lane] = r2;
        if (lane < 16) wbufv[96 + lane] = r3;
        __syncwarp();

        #pragma unroll
        for (int k = 0; k < 4; k++) {
            int idx = k * 32 + lane;                // 0..127, contiguous output sweep
            int row = idx >> 1;
            float4 v;
            if (idx & 1) {
                v = make_float4(0.0f, 0.0f, 0.0f, 0.0f);
            } else {
                float x0 = wbuf[row * 7 + 0];
                float x1 = wbuf[row * 7 + 1];
                v = make_float4(1.0f + x0, 1.0f - x0, 1.0f + x1, 1.0f - x1);
            }
            __stcs(&out4[outBase + idx], v);
        }
    } else {
        // ---- tail tile (generic, predicated) ----
        const int f4Here = (rowsHere * 7 + 3) >> 2;
        #pragma unroll
        for (int k = 0; k < 4; k++) {
            int idx = k * 32 + lane;
            if (idx < f4Here) wbufv[idx] = __ldcs(&x4[f4Base + idx]);
        }
        __syncwarp();
        #pragma unroll
        for (int k = 0; k < 4; k++) {
            int idx = k * 32 + lane;
            int row = idx >> 1;
            if (row < rowsHere) {
                float4 v;
                if (idx & 1) {
                    v = make_float4(0.0f, 0.0f, 0.0f, 0.0f);
                } else {
                    float x0 = wbuf[row * 7 + 0];
                    float x1 = wbuf[row * 7 + 1];
                    v = make_float4(1.0f + x0, 1.0f - x0, 1.0f + x1, 1.0f - x1);
                }
                __stcs(&out4[outBase + idx], v);
            }
        }
    }
}

extern "C" void kernel_launch(void* const* d_in, const int* in_sizes, int n_in,
                              void* d_out, int out_size)
{
    const float4* x4 = (const float4*)d_in[0];   // (B,7) fp32; B*7 divisible by 4
    float4* out4 = (float4*)d_out;               // (B,8) fp32 = 2 float4 per row

    const int n = in_sizes[0] / 7;               // B rows
    const int blocks = (n + ROWS_PER_BLOCK - 1) / ROWS_PER_BLOCK;
    cbf_kernel<<<blocks, THREADS>>>(x4, out4, n);
}

// round 14
// speedup vs baseline: 1.0974x; 1.0422x over previous
#include <cuda_runtime.h>

// CBFHalfspace collapses analytically:
//   h(x) = [1+x0, 1-x0, 1+x1, 1-x1];  Lfh = Lf2h = 0, LgLfh = (0,0)  (affine h, A col-sums 0)
// Output row: [1+x0, 1-x0, 1+x1, 1-x1, 0,0,0,0]. f, g are dead inputs.
//
// R11: zero-smem shuffle redistribution. Per warp-iter (32 rows = 56 float4):
//   - 2 coalesced LDG.128 (lanes 0-31 and lanes 0-23): 7 L1 wavefronts (minimum).
//   - 14 SHFLs route x0=x[7r], x1=x[7r+1] from loader lanes to store lanes
//     (SHFL rides the MIO shuffle unit, NOT the L1tex banks).
//   - 2 dense STG.128 sweeps over output: 8 L1 wavefronts (minimum).
//   L1tex per 32 rows: 24 -> 15 wavefronts vs the smem-staged R5. No smem,
//   ~35 regs -> occupancy unconstrained.

#define THREADS 256
#define WARPS 8
#define ROWS_PER_WARP 32
#define ROWS_PER_BLOCK (WARPS * ROWS_PER_WARP)   // 256
#define FULLMASK 0xFFFFFFFFu

__global__ void __launch_bounds__(THREADS)
cbf_kernel(const float4* __restrict__ x4, const float* __restrict__ xs,
           float4* __restrict__ out4, int n)
{
    const int lane = threadIdx.x & 31;
    const int wid  = threadIdx.x >> 5;

    const int warpRow0 = blockIdx.x * ROWS_PER_BLOCK + wid * ROWS_PER_WARP;
    const int rowsHere = n - warpRow0;
    if (rowsHere <= 0) return;

    const long long f4Base  = (long long)warpRow0 * 7 / 4;   // warpRow0 % 4 == 0
    const long long outBase = (long long)warpRow0 * 2;

    if (rowsHere >= ROWS_PER_WARP) {
        // ---- fast path: full 32-row tile (56 float4) ----
        float4 A = __ldcs(&x4[f4Base + lane]);               // f4[0..31]
        float4 B = make_float4(0.f, 0.f, 0.f, 0.f);
        if (lane < 24) B = __ldcs(&x4[f4Base + 32 + lane]);  // f4[32..55]

        // Lane r extracts x0 = x[7r], x1 = x[7r+1] of row r.
        const int i0 = 7 * lane;          // 0..217
        const int q  = i0 >> 2;           // 0..54
        const int c  = i0 & 3;
        const int qs = q & 31;
        const bool fromB = (q >= 32);

        float ax = __shfl_sync(FULLMASK, A.x, qs);
        float ay = __shfl_sync(FULLMASK, A.y, qs);
        float az = __shfl_sync(FULLMASK, A.z, qs);
        float aw = __shfl_sync(FULLMASK, A.w, qs);
        float bx = __shfl_sync(FULLMASK, B.x, qs);
        float by = __shfl_sync(FULLMASK, B.y, qs);
        float bz = __shfl_sync(FULLMASK, B.z, qs);
        float bw = __shfl_sync(FULLMASK, B.w, qs);

        float Qx = fromB ? bx : ax;
        float Qy = fromB ? by : ay;
        float Qz = fromB ? bz : az;
        float Qw = fromB ? bw : aw;

        // Next quad's comp0 (needed only when c == 3, i.e. r % 4 == 1).
        const int q1  = q + 1;            // <= 55
        const int q1s = q1 & 31;
        float nAx = __shfl_sync(FULLMASK, A.x, q1s);
        float nBx = __shfl_sync(FULLMASK, B.x, q1s);
        float Nx  = (q1 >= 32) ? nBx : nAx;

        float x0 = (c == 0) ? Qx : (c == 1) ? Qy : (c == 2) ? Qz : Qw;
        float x1 = (c == 0) ? Qy : (c == 1) ? Qz : (c == 2) ? Qw : Nx;

        // Redistribute onto the contiguous output sweep:
        //   store #0: out idx lane       -> row lane>>1
        //   store #1: out idx 32 + lane  -> row 16 + (lane>>1)
        const int rA = lane >> 1;
        float a0 = __shfl_sync(FULLMASK, x0, rA);
        float a1 = __shfl_sync(FULLMASK, x1, rA);
        float b0 = __shfl_sync(FULLMASK, x0, 16 + rA);
        float b1 = __shfl_sync(FULLMASK, x1, 16 + rA);

        float4 v0, v1;
        if (lane & 1) {
            v0 = make_float4(0.f, 0.f, 0.f, 0.f);
            v1 = v0;
        } else {
            v0 = make_float4(1.0f + a0, 1.0f - a0, 1.0f + a1, 1.0f - a1);
            v1 = make_float4(1.0f + b0, 1.0f - b0, 1.0f + b1, 1.0f - b1);
        }
        __stcs(&out4[outBase + lane], v0);
        __stcs(&out4[outBase + 32 + lane], v1);
    } else {
        // ---- tail tile: scalar fallback ----
        #pragma unroll
        for (int k = 0; k < 2; k++) {
            int idx = k * 32 + lane;           // output float4 index within tile
            int row = idx >> 1;
            if (row < rowsHere) {
                float4 v;
                if (idx & 1) {
                    v = make_float4(0.f, 0.f, 0.f, 0.f);
                } else {
                    long long r = (long long)(warpRow0 + row) * 7;
                    float x0 = __ldg(&xs[r + 0]);
                    float x1 = __ldg(&xs[r + 1]);
                    v = make_float4(1.0f + x0, 1.0f - x0, 1.0f + x1, 1.0f - x1);
                }
                __stcs(&out4[outBase + idx], v);
            }
        }
    }
}

extern "C" void kernel_launch(void* const* d_in, const int* in_sizes, int n_in,
                              void* d_out, int out_size)
{
    const float4* x4 = (const float4*)d_in[0];   // (B,7) fp32; B*7 divisible by 4
    const float*  xs = (const float*)d_in[0];
    float4* out4 = (float4*)d_out;               // (B,8) fp32 = 2 float4 per row

    const int n = in_sizes[0] / 7;               // B rows
    const int blocks = (n + ROWS_PER_BLOCK - 1) / ROWS_PER_BLOCK;
    cbf_kernel<<<blocks, THREADS>>>(x4, xs, out4, n);
}